// round 17
// baseline (speedup 1.0000x reference)
#include <cuda_runtime.h>

// out[oc,h,w] = sum_{k,ic} w[oc,k,ic] * xr[ic, (h-1)%14, w+k-1]   (zero pad on w+k-1)
// xr[ic,hh,j] = x[ic,hh,(j-1)%14] (W-roll); output H-roll folded into reading
// x row (h-1)%14 for output row h.
//
// Grid (14 h, 32 oc) x 128 threads = ic. Front-batched loads (MLP=10).
// ONE-BARRIER reduction: stage 1 writes TRANSPOSED part_t[wi][ic] (conflict-free
// row writes), stage 2 reads row-contiguous 16-float spans via LDS.128, then a
// 3-step shfl_xor across the aligned 8-lane octet finishes in-register.
// No part2, no second __syncthreads, no stage 3.

__global__ __launch_bounds__(128, 8)
void rolled_conv_kernel(const float* __restrict__ x,
                        const float* __restrict__ w,
                        float* __restrict__ out) {
    __shared__ float part_t[14][132];   // [wi][ic], stride 132 (4-float pad)

    const int h  = blockIdx.x;   // output row 0..13
    const int oc = blockIdx.y;   // 0..31
    const int ic = threadIdx.x;  // 0..127

    const int hm1 = (h + 13) % 14;          // x row feeding this output row

    // Front-batch ALL loads (3 w + 7 x2) -> MLP = 10, one latency exposure.
    const float* wp = w + oc * 384 + ic;
    const float w0 = __ldg(wp);
    const float w1 = __ldg(wp + 128);
    const float w2 = __ldg(wp + 256);

    // x row: 14 floats; offset ic*196 + hm1*14 is even -> 7x LDG.64
    const float2* xr2 = reinterpret_cast<const float2*>(x + ic * 196 + hm1 * 14);
    float xrow[14];
#pragma unroll
    for (int j = 0; j < 7; j++) {
        float2 v = __ldg(xr2 + j);
        xrow[2 * j]     = v.x;
        xrow[2 * j + 1] = v.y;
    }

    // Per-channel partial for each of the 14 output columns; store transposed.
    // All 32 lanes of a warp write consecutive ic within row wi -> conflict-free.
#pragma unroll
    for (int wi = 0; wi < 14; wi++) {
        float a = w1 * xrow[(wi + 13) % 14];          // k=1 tap (always valid)
        if (wi >= 1)  a += w0 * xrow[(wi + 12) % 14]; // k=0 tap
        if (wi <= 12) a += w2 * xrow[wi];             // k=2 tap
        part_t[wi][ic] = a;
    }
    __syncthreads();

    // Stage 2: t = 8*wi + g. Lane g sums part_t[wi][16g .. 16g+15] (row-contiguous,
    // 4x LDS.128), then shfl_xor 4/2/1 across the aligned octet; g==0 stores.
    {
        const int wi = threadIdx.x >> 3;   // 0..15 (14 valid)
        const int g  = threadIdx.x & 7;    // 0..7
        float s = 0.0f;
        if (wi < 14) {
            const float4* src4 = reinterpret_cast<const float4*>(&part_t[wi][g * 16]);
            float4 a = src4[0];
            float4 b = src4[1];
            float4 c = src4[2];
            float4 d = src4[3];
            float sa = (a.x + a.y) + (a.z + a.w);
            float sb = (b.x + b.y) + (b.z + b.w);
            float sc = (c.x + c.y) + (c.z + c.w);
            float sd = (d.x + d.y) + (d.z + d.w);
            s = (sa + sb) + (sc + sd);
        }
        s += __shfl_xor_sync(0xffffffffu, s, 4);
        s += __shfl_xor_sync(0xffffffffu, s, 2);
        s += __shfl_xor_sync(0xffffffffu, s, 1);

        if (g == 0 && wi < 14)
            out[oc * 196 + h * 14 + wi] = s;
    }
}

extern "C" void kernel_launch(void* const* d_in, const int* in_sizes, int n_in,
                              void* d_out, int out_size) {
    const float* x = (const float*)d_in[0];   // (1,128,14,14) = 25088 floats
    const float* w = (const float*)d_in[1];   // (32,3,128)    = 12288 floats
    float* out = (float*)d_out;               // (1,32,14,14)  = 6272 floats

    dim3 grid(14, 32);
    rolled_conv_kernel<<<grid, 128>>>(x, w, out);
}